// round 11
// baseline (speedup 1.0000x reference)
#include <cuda_runtime.h>
#include <cuda_fp16.h>
#include <math.h>
#include <stdint.h>

#define NN 4
#define LL 4096
#define HH 16
#define DD 64
#define MM 64
#define CC 128
#define GG 32
#define EPSF 1e-6f

typedef unsigned int u32;

// Scratch: per-chunk kvT stored as packed fp16 pairs (half2 along d) + fp32 ksum.
static __device__ u32   g_kvh[(size_t)NN * GG * HH * MM * (DD / 2)];   // 16.7MB
static __device__ float g_ksum[(size_t)NN * GG * HH * DD];

__device__ __forceinline__ float phi(float x) { return x > 0.f ? x + 1.f : __expf(x); }

__device__ __forceinline__ void split2h(float x0, float x1, u32& h, u32& l) {
    __half2 hh = __floats2half2_rn(x0, x1);
    float2 f = __half22float2(hh);
    __half2 ll = __floats2half2_rn(x0 - f.x, x1 - f.y);
    h = *reinterpret_cast<u32*>(&hh);
    l = *reinterpret_cast<u32*>(&ll);
}
__device__ __forceinline__ u32 rnd2h(float x0, float x1) {
    __half2 hh = __floats2half2_rn(x0, x1);
    return *reinterpret_cast<u32*>(&hh);
}
__device__ __forceinline__ float2 h2f(u32 u) {
    return __half22float2(*reinterpret_cast<__half2*>(&u));
}

__device__ __forceinline__ u32 smem_u32(const void* p) {
    u32 a;
    asm("{ .reg .u64 t; cvta.to.shared.u64 t, %1; cvt.u32.u64 %0, t; }" : "=r"(a) : "l"(p));
    return a;
}
__device__ __forceinline__ void ldm4(u32& r0, u32& r1, u32& r2, u32& r3, u32 a) {
    asm volatile("ldmatrix.sync.aligned.m8n8.x4.shared.b16 {%0,%1,%2,%3},[%4];"
                 : "=r"(r0), "=r"(r1), "=r"(r2), "=r"(r3) : "r"(a));
}
__device__ __forceinline__ void ldm4t(u32& r0, u32& r1, u32& r2, u32& r3, u32 a) {
    asm volatile("ldmatrix.sync.aligned.m8n8.x4.trans.shared.b16 {%0,%1,%2,%3},[%4];"
                 : "=r"(r0), "=r"(r1), "=r"(r2), "=r"(r3) : "r"(a));
}
__device__ __forceinline__ void ldm2(u32& r0, u32& r1, u32 a) {
    asm volatile("ldmatrix.sync.aligned.m8n8.x2.shared.b16 {%0,%1},[%2];"
                 : "=r"(r0), "=r"(r1) : "r"(a));
}
__device__ __forceinline__ void mma16816(float* d, u32 a0, u32 a1, u32 a2, u32 a3,
                                         u32 b0, u32 b1) {
    asm("mma.sync.aligned.m16n8k16.row.col.f32.f16.f16.f32 "
        "{%0,%1,%2,%3},{%4,%5,%6,%7},{%8,%9},{%0,%1,%2,%3};"
        : "+f"(d[0]), "+f"(d[1]), "+f"(d[2]), "+f"(d[3])
        : "r"(a0), "r"(a1), "r"(a2), "r"(a3), "r"(b0), "r"(b1));
}
__device__ __forceinline__ u32 off128(int row, int kb) {
    return (u32)(row * 128) + (u32)(((((kb >> 4) & 7) ^ (row & 7)) << 4) | (kb & 15));
}
__device__ __forceinline__ u32 off256(int row, int kb) {
    return (u32)(row * 256) + (u32)(kb & 128)
         + (u32)(((((kb >> 4) & 7) ^ (row & 7)) << 4) | (kb & 15));
}

// ---------------------------------------------------------------------------
// Kernel A: kvT[m][d] = sum_c v[c][m] * phi(k)[c][d]
// Natural [c][.] layout + ldmatrix.trans fragments (no transpose-scatter).
// smem: KN 16KB, VN 16KB, ksum partials 1KB.
// ---------------------------------------------------------------------------
__global__ void __launch_bounds__(256, 3) chunk_state_kernel(
    const float* __restrict__ k, const float* __restrict__ v)
{
    extern __shared__ char sm_[];
    const int KN = 0, VN = 16384, KSP = 32768;
    u32 sb = smem_u32(sm_);

    int tid = threadIdx.x, lane = tid & 31, wid = tid >> 5;
    int bid = blockIdx.x;
    int h = bid % HH;
    int gc = (bid / HH) % GG;
    int n = bid / (HH * GG);
    size_t base = (((size_t)n * LL + (size_t)gc * CC) * HH + h) * DD;

    // ---- natural-layout load: row c, 64 halves (vectorized uint2 stores) ----
    for (int i = tid; i < CC * 16; i += 256) {
        int c = i >> 4, dq = (i & 15) << 2;
        size_t off = base + (size_t)c * (HH * DD) + dq;
        float4 k4 = *(const float4*)(k + off);
        float4 v4 = *(const float4*)(v + off);
        u32 ob = off128(c, dq * 2);
        *(uint2*)(sm_ + KN + ob) =
            make_uint2(rnd2h(phi(k4.x), phi(k4.y)), rnd2h(phi(k4.z), phi(k4.w)));
        *(uint2*)(sm_ + VN + ob) =
            make_uint2(rnd2h(v4.x, v4.y), rnd2h(v4.z, v4.w));
    }
    __syncthreads();

    int grp = lane >> 2, tg = lane & 3;
    int m0 = (wid >> 1) * 16, n0 = (wid & 1) * 32;
    // trans-fragment row/col offsets (PTX ldmatrix.trans tile ordering)
    int rAt = (lane & 7) + ((lane >> 4) & 1) * 8;        // c-row (A: groups 0,1 = c0-7)
    int cAb = m0 * 2 + ((lane >> 3) & 1) * 16;           // m byte col
    int rBt = (lane & 7) + ((lane >> 3) & 1) * 8;        // c-row (B: groups 0,2 = c0-7)
    int cBb = (lane >> 4) * 16;                           // d byte col offset

    float acc[4][4] = {};
#pragma unroll
    for (int ks = 0; ks < 8; ks++) {
        u32 a0, a1, a2, a3;
        ldm4t(a0, a1, a2, a3, sb + VN + off128(ks * 16 + rAt, cAb));
#pragma unroll
        for (int jb = 0; jb < 2; jb++) {
            u32 b0, b1, b2, b3;
            ldm4t(b0, b1, b2, b3,
                  sb + KN + off128(ks * 16 + rBt, (n0 + jb * 16) * 2 + cBb));
            mma16816(acc[2 * jb],     a0, a1, a2, a3, b0, b1);
            mma16816(acc[2 * jb + 1], a0, a1, a2, a3, b2, b3);
        }
    }

    // packed fp16 write: [m][d/2] u32
    u32* kvout = g_kvh + (size_t)bid * (MM * DD / 2);
#pragma unroll
    for (int j = 0; j < 4; j++) {
        int dc = n0 + (j >> 1) * 16 + (j & 1) * 8 + tg * 2;   // even
        kvout[(size_t)(m0 + grp) * 32 + (dc >> 1)]     = rnd2h(acc[j][0], acc[j][1]);
        kvout[(size_t)(m0 + grp + 8) * 32 + (dc >> 1)] = rnd2h(acc[j][2], acc[j][3]);
    }

    // ---- ksum[d] = column sum of rounded phi(k): 4-way parallel partials ----
    {
        float* ksp = (float*)(sm_ + KSP);
        int d = tid & 63, qd = tid >> 6;
        float s = 0.f;
#pragma unroll 8
        for (int cc = 0; cc < 32; cc++)
            s += __half2float(*(const __half*)(sm_ + KN + off128(qd * 32 + cc, d * 2)));
        ksp[qd * 64 + d] = s;
    }
    __syncthreads();
    if (tid < 64) {
        const float* ksp = (const float*)(sm_ + KSP);
        g_ksum[(size_t)bid * DD + tid] =
            ksp[tid] + ksp[64 + tid] + ksp[128 + tid] + ksp[192 + tid];
    }
}

// ---------------------------------------------------------------------------
// Kernel B: exclusive prefix over chunks (fp16 storage, fp32 accumulation)
// ---------------------------------------------------------------------------
__global__ void __launch_bounds__(256) prefix_kernel()
{
    int nh = blockIdx.x >> 2, qtr = blockIdx.x & 3;
    int n = nh / HH, h = nh % HH;
    int p2 = qtr * 256 + threadIdx.x;                 // uint2 index 0..1023
    float4 run = make_float4(0.f, 0.f, 0.f, 0.f);
    for (int g = 0; g < GG; g++) {
        uint2* p = (uint2*)(g_kvh + (((size_t)(n * GG + g) * HH) + h) * (MM * DD / 2)) + p2;
        uint2 t = *p;
        float2 f0 = h2f(t.x), f1 = h2f(t.y);
        *p = make_uint2(rnd2h(run.x, run.y), rnd2h(run.z, run.w));
        run.x += f0.x; run.y += f0.y; run.z += f1.x; run.w += f1.y;
    }
    if (qtr == 0 && threadIdx.x < DD / 4) {
        float4 rs = make_float4(0.f, 0.f, 0.f, 0.f);
        for (int g = 0; g < GG; g++) {
            float4* p = (float4*)(g_ksum + (((size_t)(n * GG + g) * HH) + h) * DD) + threadIdx.x;
            float4 t = *p;
            *p = rs;
            rs.x += t.x; rs.y += t.y; rs.z += t.z; rs.w += t.w;
        }
    }
}

// ---------------------------------------------------------------------------
// Kernel C: fp16 2-pass, fused z, triangle skip, CORRECT SMSP balance
// (SMSP id = wid % 4 -> pair wb so each SMSP sums to 9 units).
// ---------------------------------------------------------------------------
#define QHo 0
#define QLo 16384
#define KHo 32768
#define VHo 49152
#define WHo 67584
#define SMEM_C 76800

__global__ void __launch_bounds__(256, 2) output_kernel(
    const float* __restrict__ q, const float* __restrict__ k,
    const float* __restrict__ v, float* __restrict__ out)
{
    extern __shared__ char sm_[];
    u32 sb = smem_u32(sm_);

    int tid = threadIdx.x, lane = tid & 31, wid = tid >> 5;
    int bid = blockIdx.x;
    int h = bid % HH;
    int gc = (bid / HH) % GG;
    int n = bid / (HH * GG);
    size_t base = (((size_t)n * LL + (size_t)gc * CC) * HH + h) * DD;

    // ---- Q (split) and K (rounded) rows ----
    for (int i = tid; i < CC * 16; i += 256) {
        int c = i >> 4, dq = (i & 15) << 2;
        size_t off = base + (size_t)c * (HH * DD) + dq;
        float4 q4 = *(const float4*)(q + off);
        float4 k4 = *(const float4*)(k + off);
        u32 ob = off128(c, dq * 2);
        u32 h01, l01, h23, l23;
        split2h(phi(q4.x), phi(q4.y), h01, l01);
        split2h(phi(q4.z), phi(q4.w), h23, l23);
        *(uint2*)(sm_ + QHo + ob) = make_uint2(h01, h23);
        *(uint2*)(sm_ + QLo + ob) = make_uint2(l01, l23);
        *(uint2*)(sm_ + KHo + ob) =
            make_uint2(rnd2h(phi(k4.x), phi(k4.y)), rnd2h(phi(k4.z), phi(k4.w)));
    }
    // ---- V transposed (rounded) rows 0..63 ----
    {
        int e0 = (tid & 15) * 4;
#pragma unroll
        for (int it = 0; it < 4; it++) {
            int cp = it * 16 + (tid >> 4);
            size_t off0 = base + (size_t)(cp * 2) * (HH * DD) + e0;
            float4 va = *(const float4*)(v + off0);
            float4 vb = *(const float4*)(v + off0 + HH * DD);
            float fa[4] = { va.x, va.y, va.z, va.w };
            float fb[4] = { vb.x, vb.y, vb.z, vb.w };
#pragma unroll
            for (int t = 0; t < 4; t++)
                *(u32*)(sm_ + VHo + off256(e0 + t, cp * 4)) = rnd2h(fa[t], fb[t]);
        }
    }
    // ---- KV' rows 0..63: straight fp16 copy (1024 uint2 = full 8KB plane) ----
    {
        const u32* kvp = g_kvh + (size_t)bid * (MM * DD / 2);
        for (int i = tid; i < 1024; i += 256) {
            int m = i >> 4, du = (i & 15) * 2;        // u32 index within row
            uint2 t = *(const uint2*)(kvp + (size_t)m * 32 + du);
            *(uint2*)(sm_ + WHo + off128(m, du * 4)) = t;
        }
    }
    // ---- KV' row 64 = ksum_prev ----
    if (tid < 16) {
        float4 t4 = *(const float4*)(g_ksum + (size_t)bid * DD + tid * 4);
        *(uint2*)(sm_ + WHo + off128(64, tid * 8)) =
            make_uint2(rnd2h(t4.x, t4.y), rnd2h(t4.z, t4.w));
    }
    // ---- V' rows 64..71 (ones / zero), KV' rows 65..71 zero ----
    for (int i = tid; i < 512; i += 256) {
        int row = 64 + (i >> 6), cu = i & 63;
        *(u32*)(sm_ + VHo + row * 256 + cu * 4) = (row == 64) ? 0x3C003C00u : 0u;
    }
    if (tid < 224) {
        int row = 65 + (tid >> 5), cu = tid & 31;
        *(u32*)(sm_ + WHo + row * 128 + cu * 4) = 0u;
    }
    __syncthreads();

    // SMSP = wid % 4: pair wb values so each SMSP carries 9 triangle units.
    const int perm[8] = { 0, 1, 2, 3, 7, 6, 5, 4 };
    int wb = perm[wid];
    int m0 = wb * 16;
    int grp = lane >> 2, tg = lane & 3;
    int rA = m0 + ((lane >> 3) & 1) * 8 + (lane & 7);
    int rB = (lane >> 4) * 8 + (lane & 7);
    int kbA0 = 16 * (lane >> 4);
    int kbB0 = 16 * ((lane >> 3) & 1);
    int r9 = 64 + (lane & 7);
    int r0 = m0 + grp, r1 = r0 + 8;

    // ---- cache Q fragments ----
    u32 qh[4][4], ql[4][4];
#pragma unroll
    for (int ks = 0; ks < 4; ks++) {
        ldm4(qh[ks][0], qh[ks][1], qh[ks][2], qh[ks][3], sb + QHo + off128(rA, 32 * ks + kbA0));
        ldm4(ql[ks][0], ql[ks][1], ql[ks][2], ql[ks][3], sb + QLo + off128(rA, 32 * ks + kbA0));
    }

    float accO[9][4] = {};

    // ---- inter: O += Q KV'^T (N=72, z col 64) ----
#pragma unroll
    for (int ks = 0; ks < 4; ks++) {
        int kb = 32 * ks + kbB0;
#pragma unroll
        for (int jb = 0; jb < 4; jb++) {
            u32 b0, b1, b2, b3;
            ldm4(b0, b1, b2, b3, sb + WHo + off128(jb * 16 + rB, kb));
            mma16816(accO[2 * jb],     qh[ks][0], qh[ks][1], qh[ks][2], qh[ks][3], b0, b1);
            mma16816(accO[2 * jb + 1], qh[ks][0], qh[ks][1], qh[ks][2], qh[ks][3], b2, b3);
            mma16816(accO[2 * jb],     ql[ks][0], ql[ks][1], ql[ks][2], ql[ks][3], b0, b1);
            mma16816(accO[2 * jb + 1], ql[ks][0], ql[ks][1], ql[ks][2], ql[ks][3], b2, b3);
        }
        u32 b0, b1;
        ldm2(b0, b1, sb + WHo + off128(r9, kb));
        mma16816(accO[8], qh[ks][0], qh[ks][1], qh[ks][2], qh[ks][3], b0, b1);
        mma16816(accO[8], ql[ks][0], ql[ks][1], ql[ks][2], ql[ks][3], b0, b1);
    }

    // ---- S blocks (jb <= wb): GEMM1 block -> mask -> split -> intra ----
#pragma unroll
    for (int jb = 0; jb < 8; jb++) {
        if (jb <= wb) {
            float s0[4] = {}, s1[4] = {};
#pragma unroll
            for (int ks = 0; ks < 4; ks++) {
                u32 b0, b1, b2, b3;
                ldm4(b0, b1, b2, b3, sb + KHo + off128(jb * 16 + rB, 32 * ks + kbB0));
                mma16816(s0, qh[ks][0], qh[ks][1], qh[ks][2], qh[ks][3], b0, b1);
                mma16816(s1, qh[ks][0], qh[ks][1], qh[ks][2], qh[ks][3], b2, b3);
                mma16816(s0, ql[ks][0], ql[ks][1], ql[ks][2], ql[ks][3], b0, b1);
                mma16816(s1, ql[ks][0], ql[ks][1], ql[ks][2], ql[ks][3], b2, b3);
            }
            int cA = jb * 16 + tg * 2, cB = cA + 8;
            if (cA > r0)     s0[0] = 0.f;
            if (cA + 1 > r0) s0[1] = 0.f;
            if (cA > r1)     s0[2] = 0.f;
            if (cA + 1 > r1) s0[3] = 0.f;
            if (cB > r0)     s1[0] = 0.f;
            if (cB + 1 > r0) s1[1] = 0.f;
            if (cB > r1)     s1[2] = 0.f;
            if (cB + 1 > r1) s1[3] = 0.f;
            u32 sh0, sh1, sh2, sh3, sl0, sl1, sl2, sl3;
            split2h(s0[0], s0[1], sh0, sl0);
            split2h(s0[2], s0[3], sh1, sl1);
            split2h(s1[0], s1[1], sh2, sl2);
            split2h(s1[2], s1[3], sh3, sl3);
            int kb2 = 32 * jb + kbB0;
#pragma unroll
            for (int vjb = 0; vjb < 4; vjb++) {
                u32 b0, b1, b2, b3;
                ldm4(b0, b1, b2, b3, sb + VHo + off256(vjb * 16 + rB, kb2));
                mma16816(accO[2 * vjb],     sh0, sh1, sh2, sh3, b0, b1);
                mma16816(accO[2 * vjb + 1], sh0, sh1, sh2, sh3, b2, b3);
                mma16816(accO[2 * vjb],     sl0, sl1, sl2, sl3, b0, b1);
                mma16816(accO[2 * vjb + 1], sl0, sl1, sl2, sl3, b2, b3);
            }
            u32 b0, b1;
            ldm2(b0, b1, sb + VHo + off256(r9, kb2));
            mma16816(accO[8], sh0, sh1, sh2, sh3, b0, b1);
            mma16816(accO[8], sl0, sl1, sl2, sl3, b0, b1);
        }
    }

    // ---- normalize + store ----
    float zr0 = __shfl_sync(0xffffffffu, accO[8][0], lane & 28);
    float zr1 = __shfl_sync(0xffffffffu, accO[8][2], lane & 28);
    float rz0 = 1.0f / (zr0 + EPSF);
    float rz1 = 1.0f / (zr1 + EPSF);
    float* op0 = out + (((size_t)n * LL + (size_t)gc * CC + r0) * HH + h) * MM;
    float* op1 = op0 + (size_t)8 * HH * MM;
#pragma unroll
    for (int j = 0; j < 8; j++) {
        int c0 = j * 8 + tg * 2;
        *(float2*)(op0 + c0) = make_float2(accO[j][0] * rz0, accO[j][1] * rz0);
        *(float2*)(op1 + c0) = make_float2(accO[j][2] * rz1, accO[j][3] * rz1);
    }
}

// ---------------------------------------------------------------------------
extern "C" void kernel_launch(void* const* d_in, const int* in_sizes, int n_in,
                              void* d_out, int out_size)
{
    const float* q = (const float*)d_in[0];
    const float* k = (const float*)d_in[1];
    const float* v = (const float*)d_in[2];
    float* out = (float*)d_out;

    const int SMEM_A = 33792;

    cudaFuncSetAttribute(chunk_state_kernel,
                         cudaFuncAttributeMaxDynamicSharedMemorySize, SMEM_A);
    cudaFuncSetAttribute(output_kernel,
                         cudaFuncAttributeMaxDynamicSharedMemorySize, SMEM_C);

    chunk_state_kernel<<<NN * GG * HH, 256, SMEM_A>>>(k, v);
    prefix_kernel<<<NN * HH * 4, 256>>>();
    output_kernel<<<NN * GG * HH, 256, SMEM_C>>>(q, k, v, out);
}

// round 12
// speedup vs baseline: 1.0699x; 1.0699x over previous
#include <cuda_runtime.h>
#include <cuda_fp16.h>
#include <math.h>
#include <stdint.h>

#define NN 4
#define LL 4096
#define HH 16
#define DD 64
#define MM 64
#define CC 128
#define GG 32
#define EPSF 1e-6f

typedef unsigned int u32;

// Scratch: per-chunk kvT stored as packed fp16 pairs (half2 along d) + fp32 ksum.
static __device__ u32   g_kvh[(size_t)NN * GG * HH * MM * (DD / 2)];   // 16.7MB
static __device__ float g_ksum[(size_t)NN * GG * HH * DD];

__device__ __forceinline__ float phi(float x) { return x > 0.f ? x + 1.f : __expf(x); }

__device__ __forceinline__ void split2h(float x0, float x1, u32& h, u32& l) {
    __half2 hh = __floats2half2_rn(x0, x1);
    float2 f = __half22float2(hh);
    __half2 ll = __floats2half2_rn(x0 - f.x, x1 - f.y);
    h = *reinterpret_cast<u32*>(&hh);
    l = *reinterpret_cast<u32*>(&ll);
}
__device__ __forceinline__ u32 rnd2h(float x0, float x1) {
    __half2 hh = __floats2half2_rn(x0, x1);
    return *reinterpret_cast<u32*>(&hh);
}
__device__ __forceinline__ float2 h2f(u32 u) {
    return __half22float2(*reinterpret_cast<__half2*>(&u));
}

__device__ __forceinline__ u32 smem_u32(const void* p) {
    u32 a;
    asm("{ .reg .u64 t; cvta.to.shared.u64 t, %1; cvt.u32.u64 %0, t; }" : "=r"(a) : "l"(p));
    return a;
}
__device__ __forceinline__ void ldm4(u32& r0, u32& r1, u32& r2, u32& r3, u32 a) {
    asm volatile("ldmatrix.sync.aligned.m8n8.x4.shared.b16 {%0,%1,%2,%3},[%4];"
                 : "=r"(r0), "=r"(r1), "=r"(r2), "=r"(r3) : "r"(a));
}
__device__ __forceinline__ void ldm4t(u32& r0, u32& r1, u32& r2, u32& r3, u32 a) {
    asm volatile("ldmatrix.sync.aligned.m8n8.x4.trans.shared.b16 {%0,%1,%2,%3},[%4];"
                 : "=r"(r0), "=r"(r1), "=r"(r2), "=r"(r3) : "r"(a));
}
__device__ __forceinline__ void ldm2(u32& r0, u32& r1, u32 a) {
    asm volatile("ldmatrix.sync.aligned.m8n8.x2.shared.b16 {%0,%1},[%2];"
                 : "=r"(r0), "=r"(r1) : "r"(a));
}
__device__ __forceinline__ void mma16816(float* d, u32 a0, u32 a1, u32 a2, u32 a3,
                                         u32 b0, u32 b1) {
    asm("mma.sync.aligned.m16n8k16.row.col.f32.f16.f16.f32 "
        "{%0,%1,%2,%3},{%4,%5,%6,%7},{%8,%9},{%0,%1,%2,%3};"
        : "+f"(d[0]), "+f"(d[1]), "+f"(d[2]), "+f"(d[3])
        : "r"(a0), "r"(a1), "r"(a2), "r"(a3), "r"(b0), "r"(b1));
}
__device__ __forceinline__ u32 off128(int row, int kb) {
    return (u32)(row * 128) + (u32)(((((kb >> 4) & 7) ^ (row & 7)) << 4) | (kb & 15));
}
__device__ __forceinline__ u32 off256(int row, int kb) {
    return (u32)(row * 256) + (u32)(kb & 128)
         + (u32)(((((kb >> 4) & 7) ^ (row & 7)) << 4) | (kb & 15));
}

// ---------------------------------------------------------------------------
// Kernel A: kvT[m][d] = sum_c v[c][m] * phi(k)[c][d]
// Natural [c][.] layout + ldmatrix.trans fragments. Batched LDG (MLP ~8).
// ---------------------------------------------------------------------------
__global__ void __launch_bounds__(256, 3) chunk_state_kernel(
    const float* __restrict__ k, const float* __restrict__ v)
{
    extern __shared__ char sm_[];
    const int KN = 0, VN = 16384, KSP = 32768;
    u32 sb = smem_u32(sm_);

    int tid = threadIdx.x, lane = tid & 31, wid = tid >> 5;
    int bid = blockIdx.x;
    int h = bid % HH;
    int gc = (bid / HH) % GG;
    int n = bid / (HH * GG);
    size_t base = (((size_t)n * LL + (size_t)gc * CC) * HH + h) * DD;

    // ---- batched natural-layout load (8 LDG.128 in flight per half) ----
#pragma unroll
    for (int hb = 0; hb < 2; hb++) {
        float4 kr[4], vr[4];
#pragma unroll
        for (int t = 0; t < 4; t++) {
            int i = tid + (hb * 4 + t) * 256;
            int c = i >> 4, dq = (i & 15) << 2;
            size_t off = base + (size_t)c * (HH * DD) + dq;
            kr[t] = *(const float4*)(k + off);
            vr[t] = *(const float4*)(v + off);
        }
#pragma unroll
        for (int t = 0; t < 4; t++) {
            int i = tid + (hb * 4 + t) * 256;
            int c = i >> 4, dq = (i & 15) << 2;
            u32 ob = off128(c, dq * 2);
            *(uint2*)(sm_ + KN + ob) =
                make_uint2(rnd2h(phi(kr[t].x), phi(kr[t].y)),
                           rnd2h(phi(kr[t].z), phi(kr[t].w)));
            *(uint2*)(sm_ + VN + ob) =
                make_uint2(rnd2h(vr[t].x, vr[t].y), rnd2h(vr[t].z, vr[t].w));
        }
    }
    __syncthreads();

    int grp = lane >> 2, tg = lane & 3;
    int m0 = (wid >> 1) * 16, n0 = (wid & 1) * 32;
    int rAt = (lane & 7) + ((lane >> 4) & 1) * 8;
    int cAb = m0 * 2 + ((lane >> 3) & 1) * 16;
    int rBt = (lane & 7) + ((lane >> 3) & 1) * 8;
    int cBb = (lane >> 4) * 16;

    float acc[4][4] = {};
#pragma unroll
    for (int ks = 0; ks < 8; ks++) {
        u32 a0, a1, a2, a3;
        ldm4t(a0, a1, a2, a3, sb + VN + off128(ks * 16 + rAt, cAb));
#pragma unroll
        for (int jb = 0; jb < 2; jb++) {
            u32 b0, b1, b2, b3;
            ldm4t(b0, b1, b2, b3,
                  sb + KN + off128(ks * 16 + rBt, (n0 + jb * 16) * 2 + cBb));
            mma16816(acc[2 * jb],     a0, a1, a2, a3, b0, b1);
            mma16816(acc[2 * jb + 1], a0, a1, a2, a3, b2, b3);
        }
    }

    u32* kvout = g_kvh + (size_t)bid * (MM * DD / 2);
#pragma unroll
    for (int j = 0; j < 4; j++) {
        int dc = n0 + (j >> 1) * 16 + (j & 1) * 8 + tg * 2;
        kvout[(size_t)(m0 + grp) * 32 + (dc >> 1)]     = rnd2h(acc[j][0], acc[j][1]);
        kvout[(size_t)(m0 + grp + 8) * 32 + (dc >> 1)] = rnd2h(acc[j][2], acc[j][3]);
    }

    {
        float* ksp = (float*)(sm_ + KSP);
        int d = tid & 63, qd = tid >> 6;
        float s = 0.f;
#pragma unroll 8
        for (int cc = 0; cc < 32; cc++)
            s += __half2float(*(const __half*)(sm_ + KN + off128(qd * 32 + cc, d * 2)));
        ksp[qd * 64 + d] = s;
    }
    __syncthreads();
    if (tid < 64) {
        const float* ksp = (const float*)(sm_ + KSP);
        g_ksum[(size_t)bid * DD + tid] =
            ksp[tid] + ksp[64 + tid] + ksp[128 + tid] + ksp[192 + tid];
    }
}

// ---------------------------------------------------------------------------
// Kernel B: exclusive prefix over chunks (fp16 storage, fp32 accumulation)
// ---------------------------------------------------------------------------
__global__ void __launch_bounds__(256) prefix_kernel()
{
    int nh = blockIdx.x >> 2, qtr = blockIdx.x & 3;
    int n = nh / HH, h = nh % HH;
    int p2 = qtr * 256 + threadIdx.x;
    float4 run = make_float4(0.f, 0.f, 0.f, 0.f);
    for (int g = 0; g < GG; g++) {
        uint2* p = (uint2*)(g_kvh + (((size_t)(n * GG + g) * HH) + h) * (MM * DD / 2)) + p2;
        uint2 t = *p;
        float2 f0 = h2f(t.x), f1 = h2f(t.y);
        *p = make_uint2(rnd2h(run.x, run.y), rnd2h(run.z, run.w));
        run.x += f0.x; run.y += f0.y; run.z += f1.x; run.w += f1.y;
    }
    if (qtr == 0 && threadIdx.x < DD / 4) {
        float4 rs = make_float4(0.f, 0.f, 0.f, 0.f);
        for (int g = 0; g < GG; g++) {
            float4* p = (float4*)(g_ksum + (((size_t)(n * GG + g) * HH) + h) * DD) + threadIdx.x;
            float4 t = *p;
            *p = rs;
            rs.x += t.x; rs.y += t.y; rs.z += t.z; rs.w += t.w;
        }
    }
}

// ---------------------------------------------------------------------------
// Kernel C: fp16 2-pass, fused z, triangle skip; natural V + ldm4t intra B;
// merged/batched q,k,v loader.
// smem planes (bytes): QH 0, QL 16K, KH 32K (128x128B);
//   VN 48K natural V (128x128B); ZP 64K ones-plane (8x256B);
//   WH 66K KV'+ksum (72x128B).  total 75KB.
// ---------------------------------------------------------------------------
#define QHo 0
#define QLo 16384
#define KHo 32768
#define VNo 49152
#define ZPo 65536
#define WHo 67584
#define SMEM_C 76800

__global__ void __launch_bounds__(256, 2) output_kernel(
    const float* __restrict__ q, const float* __restrict__ k,
    const float* __restrict__ v, float* __restrict__ out)
{
    extern __shared__ char sm_[];
    u32 sb = smem_u32(sm_);

    int tid = threadIdx.x, lane = tid & 31, wid = tid >> 5;
    int bid = blockIdx.x;
    int h = bid % HH;
    int gc = (bid / HH) % GG;
    int n = bid / (HH * GG);
    size_t base = (((size_t)n * LL + (size_t)gc * CC) * HH + h) * DD;

    // ---- merged, batched q/k/v loader (6 LDG.128 in flight per batch) ----
#pragma unroll
    for (int bb = 0; bb < 4; bb++) {
        float4 qr[2], kr[2], vr[2];
#pragma unroll
        for (int t = 0; t < 2; t++) {
            int i = tid + (bb * 2 + t) * 256;
            int c = i >> 4, dq = (i & 15) << 2;
            size_t off = base + (size_t)c * (HH * DD) + dq;
            qr[t] = *(const float4*)(q + off);
            kr[t] = *(const float4*)(k + off);
            vr[t] = *(const float4*)(v + off);
        }
#pragma unroll
        for (int t = 0; t < 2; t++) {
            int i = tid + (bb * 2 + t) * 256;
            int c = i >> 4, dq = (i & 15) << 2;
            u32 ob = off128(c, dq * 2);
            u32 h01, l01, h23, l23;
            split2h(phi(qr[t].x), phi(qr[t].y), h01, l01);
            split2h(phi(qr[t].z), phi(qr[t].w), h23, l23);
            *(uint2*)(sm_ + QHo + ob) = make_uint2(h01, h23);
            *(uint2*)(sm_ + QLo + ob) = make_uint2(l01, l23);
            *(uint2*)(sm_ + KHo + ob) =
                make_uint2(rnd2h(phi(kr[t].x), phi(kr[t].y)),
                           rnd2h(phi(kr[t].z), phi(kr[t].w)));
            *(uint2*)(sm_ + VNo + ob) =
                make_uint2(rnd2h(vr[t].x, vr[t].y), rnd2h(vr[t].z, vr[t].w));
        }
    }
    // ---- KV' rows 0..63: straight fp16 copy (1024 uint2) ----
    {
        const u32* kvp = g_kvh + (size_t)bid * (MM * DD / 2);
        for (int i = tid; i < 1024; i += 256) {
            int m = i >> 4, du = (i & 15) * 2;
            uint2 t = *(const uint2*)(kvp + (size_t)m * 32 + du);
            *(uint2*)(sm_ + WHo + off128(m, du * 4)) = t;
        }
    }
    // ---- KV' row 64 = ksum_prev ----
    if (tid < 16) {
        float4 t4 = *(const float4*)(g_ksum + (size_t)bid * DD + tid * 4);
        *(uint2*)(sm_ + WHo + off128(64, tid * 8)) =
            make_uint2(rnd2h(t4.x, t4.y), rnd2h(t4.z, t4.w));
    }
    // ---- ZP ones-plane (row 0 ones, rows 1..7 zero; constant rows are
    //      swizzle-invariant so linear stores are fine) ----
    for (int i = tid; i < 512; i += 256) {
        int row = i >> 6, cu = i & 63;
        *(u32*)(sm_ + ZPo + row * 256 + cu * 4) = (row == 0) ? 0x3C003C00u : 0u;
    }
    // ---- KV' rows 65..71 zero ----
    if (tid < 224) {
        int row = 65 + (tid >> 5), cu = tid & 31;
        *(u32*)(sm_ + WHo + row * 128 + cu * 4) = 0u;
    }
    __syncthreads();

    const int perm[8] = { 0, 1, 2, 3, 7, 6, 5, 4 };
    int wb = perm[wid];
    int m0 = wb * 16;
    int grp = lane >> 2, tg = lane & 3;
    int rA = m0 + ((lane >> 3) & 1) * 8 + (lane & 7);
    int rB = (lane >> 4) * 8 + (lane & 7);
    int kbA0 = 16 * (lane >> 4);
    int kbB0 = 16 * ((lane >> 3) & 1);
    int rBt = (lane & 7) + ((lane >> 3) & 1) * 8;   // natural-V trans B
    int cBb = (lane >> 4) * 16;
    int rz = lane & 7;                               // ZP plane row
    int r9 = 64 + (lane & 7);                        // WH plane z row
    int r0 = m0 + grp, r1 = r0 + 8;

    // ---- cache Q fragments ----
    u32 qh[4][4], ql[4][4];
#pragma unroll
    for (int ks = 0; ks < 4; ks++) {
        ldm4(qh[ks][0], qh[ks][1], qh[ks][2], qh[ks][3], sb + QHo + off128(rA, 32 * ks + kbA0));
        ldm4(ql[ks][0], ql[ks][1], ql[ks][2], ql[ks][3], sb + QLo + off128(rA, 32 * ks + kbA0));
    }

    float accO[9][4] = {};

    // ---- inter: O += Q KV'^T (N=72, z col 64) ----
#pragma unroll
    for (int ks = 0; ks < 4; ks++) {
        int kb = 32 * ks + kbB0;
#pragma unroll
        for (int jb = 0; jb < 4; jb++) {
            u32 b0, b1, b2, b3;
            ldm4(b0, b1, b2, b3, sb + WHo + off128(jb * 16 + rB, kb));
            mma16816(accO[2 * jb],     qh[ks][0], qh[ks][1], qh[ks][2], qh[ks][3], b0, b1);
            mma16816(accO[2 * jb + 1], qh[ks][0], qh[ks][1], qh[ks][2], qh[ks][3], b2, b3);
            mma16816(accO[2 * jb],     ql[ks][0], ql[ks][1], ql[ks][2], ql[ks][3], b0, b1);
            mma16816(accO[2 * jb + 1], ql[ks][0], ql[ks][1], ql[ks][2], ql[ks][3], b2, b3);
        }
        u32 b0, b1;
        ldm2(b0, b1, sb + WHo + off128(r9, kb));
        mma16816(accO[8], qh[ks][0], qh[ks][1], qh[ks][2], qh[ks][3], b0, b1);
        mma16816(accO[8], ql[ks][0], ql[ks][1], ql[ks][2], ql[ks][3], b0, b1);
    }

    // ---- S blocks (jb <= wb): GEMM1 block -> mask -> split -> intra ----
#pragma unroll
    for (int jb = 0; jb < 8; jb++) {
        if (jb <= wb) {
            float s0[4] = {}, s1[4] = {};
#pragma unroll
            for (int ks = 0; ks < 4; ks++) {
                u32 b0, b1, b2, b3;
                ldm4(b0, b1, b2, b3, sb + KHo + off128(jb * 16 + rB, 32 * ks + kbB0));
                mma16816(s0, qh[ks][0], qh[ks][1], qh[ks][2], qh[ks][3], b0, b1);
                mma16816(s1, qh[ks][0], qh[ks][1], qh[ks][2], qh[ks][3], b2, b3);
                mma16816(s0, ql[ks][0], ql[ks][1], ql[ks][2], ql[ks][3], b0, b1);
                mma16816(s1, ql[ks][0], ql[ks][1], ql[ks][2], ql[ks][3], b2, b3);
            }
            int cA = jb * 16 + tg * 2, cB = cA + 8;
            if (cA > r0)     s0[0] = 0.f;
            if (cA + 1 > r0) s0[1] = 0.f;
            if (cA > r1)     s0[2] = 0.f;
            if (cA + 1 > r1) s0[3] = 0.f;
            if (cB > r0)     s1[0] = 0.f;
            if (cB + 1 > r0) s1[1] = 0.f;
            if (cB > r1)     s1[2] = 0.f;
            if (cB + 1 > r1) s1[3] = 0.f;
            u32 sh0, sh1, sh2, sh3, sl0, sl1, sl2, sl3;
            split2h(s0[0], s0[1], sh0, sl0);
            split2h(s0[2], s0[3], sh1, sl1);
            split2h(s1[0], s1[1], sh2, sl2);
            split2h(s1[2], s1[3], sh3, sl3);
            int kb2 = 32 * jb + kbB0;
#pragma unroll
            for (int vjb = 0; vjb < 4; vjb++) {
                u32 b0, b1, b2, b3;
                // natural V, transposed fragment (same mapping as kernel A)
                ldm4t(b0, b1, b2, b3,
                      sb + VNo + off128(jb * 16 + rBt, vjb * 32 + cBb));
                mma16816(accO[2 * vjb],     sh0, sh1, sh2, sh3, b0, b1);
                mma16816(accO[2 * vjb + 1], sh0, sh1, sh2, sh3, b2, b3);
                mma16816(accO[2 * vjb],     sl0, sl1, sl2, sl3, b0, b1);
                mma16816(accO[2 * vjb + 1], sl0, sl1, sl2, sl3, b2, b3);
            }
            u32 b0, b1;
            ldm2(b0, b1, sb + ZPo + off256(rz, kb2));
            mma16816(accO[8], sh0, sh1, sh2, sh3, b0, b1);
            mma16816(accO[8], sl0, sl1, sl2, sl3, b0, b1);
        }
    }

    // ---- normalize + store ----
    float zr0 = __shfl_sync(0xffffffffu, accO[8][0], lane & 28);
    float zr1 = __shfl_sync(0xffffffffu, accO[8][2], lane & 28);
    float rz0 = 1.0f / (zr0 + EPSF);
    float rz1 = 1.0f / (zr1 + EPSF);
    float* op0 = out + (((size_t)n * LL + (size_t)gc * CC + r0) * HH + h) * MM;
    float* op1 = op0 + (size_t)8 * HH * MM;
#pragma unroll
    for (int j = 0; j < 8; j++) {
        int c0 = j * 8 + tg * 2;
        *(float2*)(op0 + c0) = make_float2(accO[j][0] * rz0, accO[j][1] * rz0);
        *(float2*)(op1 + c0) = make_float2(accO[j][2] * rz1, accO[j][3] * rz1);
    }
}

// ---------------------------------------------------------------------------
extern "C" void kernel_launch(void* const* d_in, const int* in_sizes, int n_in,
                              void* d_out, int out_size)
{
    const float* q = (const float*)d_in[0];
    const float* k = (const float*)d_in[1];
    const float* v = (const float*)d_in[2];
    float* out = (float*)d_out;

    const int SMEM_A = 33792;

    cudaFuncSetAttribute(chunk_state_kernel,
                         cudaFuncAttributeMaxDynamicSharedMemorySize, SMEM_A);
    cudaFuncSetAttribute(output_kernel,
                         cudaFuncAttributeMaxDynamicSharedMemorySize, SMEM_C);

    chunk_state_kernel<<<NN * GG * HH, 256, SMEM_A>>>(k, v);
    prefix_kernel<<<NN * HH * 4, 256>>>();
    output_kernel<<<NN * GG * HH, 256, SMEM_C>>>(q, k, v, out);
}

// round 13
// speedup vs baseline: 1.1898x; 1.1121x over previous
#include <cuda_runtime.h>
#include <cuda_fp16.h>
#include <math.h>
#include <stdint.h>

#define NN 4
#define LL 4096
#define HH 16
#define DD 64
#define MM 64
#define CC 128
#define GG 32
#define EPSF 1e-6f

typedef unsigned int u32;

// Scratch: per-chunk kvT stored as packed fp16 pairs (half2 along d) + fp32 ksum.
static __device__ u32   g_kvh[(size_t)NN * GG * HH * MM * (DD / 2)];   // 16.7MB
static __device__ float g_ksum[(size_t)NN * GG * HH * DD];

__device__ __forceinline__ float phi(float x) { return x > 0.f ? x + 1.f : __expf(x); }

__device__ __forceinline__ void split2h(float x0, float x1, u32& h, u32& l) {
    __half2 hh = __floats2half2_rn(x0, x1);
    float2 f = __half22float2(hh);
    __half2 ll = __floats2half2_rn(x0 - f.x, x1 - f.y);
    h = *reinterpret_cast<u32*>(&hh);
    l = *reinterpret_cast<u32*>(&ll);
}
__device__ __forceinline__ u32 rnd2h(float x0, float x1) {
    __half2 hh = __floats2half2_rn(x0, x1);
    return *reinterpret_cast<u32*>(&hh);
}
__device__ __forceinline__ float2 h2f(u32 u) {
    return __half22float2(*reinterpret_cast<__half2*>(&u));
}

__device__ __forceinline__ u32 smem_u32(const void* p) {
    u32 a;
    asm("{ .reg .u64 t; cvta.to.shared.u64 t, %1; cvt.u32.u64 %0, t; }" : "=r"(a) : "l"(p));
    return a;
}
__device__ __forceinline__ void ldm4(u32& r0, u32& r1, u32& r2, u32& r3, u32 a) {
    asm volatile("ldmatrix.sync.aligned.m8n8.x4.shared.b16 {%0,%1,%2,%3},[%4];"
                 : "=r"(r0), "=r"(r1), "=r"(r2), "=r"(r3) : "r"(a));
}
__device__ __forceinline__ void ldm4t(u32& r0, u32& r1, u32& r2, u32& r3, u32 a) {
    asm volatile("ldmatrix.sync.aligned.m8n8.x4.trans.shared.b16 {%0,%1,%2,%3},[%4];"
                 : "=r"(r0), "=r"(r1), "=r"(r2), "=r"(r3) : "r"(a));
}
__device__ __forceinline__ void ldm2(u32& r0, u32& r1, u32 a) {
    asm volatile("ldmatrix.sync.aligned.m8n8.x2.shared.b16 {%0,%1},[%2];"
                 : "=r"(r0), "=r"(r1) : "r"(a));
}
__device__ __forceinline__ void mma16816(float* d, u32 a0, u32 a1, u32 a2, u32 a3,
                                         u32 b0, u32 b1) {
    asm("mma.sync.aligned.m16n8k16.row.col.f32.f16.f16.f32 "
        "{%0,%1,%2,%3},{%4,%5,%6,%7},{%8,%9},{%0,%1,%2,%3};"
        : "+f"(d[0]), "+f"(d[1]), "+f"(d[2]), "+f"(d[3])
        : "r"(a0), "r"(a1), "r"(a2), "r"(a3), "r"(b0), "r"(b1));
}
__device__ __forceinline__ u32 off128(int row, int kb) {
    return (u32)(row * 128) + (u32)(((((kb >> 4) & 7) ^ (row & 7)) << 4) | (kb & 15));
}
__device__ __forceinline__ u32 off256(int row, int kb) {
    return (u32)(row * 256) + (u32)(kb & 128)
         + (u32)(((((kb >> 4) & 7) ^ (row & 7)) << 4) | (kb & 15));
}

// ---------------------------------------------------------------------------
// Kernel A: kvT[m][d] = sum_c v[c][m] * phi(k)[c][d]
// Natural [c][.] layout + ldmatrix.trans fragments. Batched LDG (MLP ~8).
// ---------------------------------------------------------------------------
__global__ void __launch_bounds__(256, 3) chunk_state_kernel(
    const float* __restrict__ k, const float* __restrict__ v)
{
    extern __shared__ char sm_[];
    const int KN = 0, VN = 16384, KSP = 32768;
    u32 sb = smem_u32(sm_);

    int tid = threadIdx.x, lane = tid & 31, wid = tid >> 5;
    int bid = blockIdx.x;
    int h = bid % HH;
    int gc = (bid / HH) % GG;
    int n = bid / (HH * GG);
    size_t base = (((size_t)n * LL + (size_t)gc * CC) * HH + h) * DD;

#pragma unroll
    for (int hb = 0; hb < 2; hb++) {
        float4 kr[4], vr[4];
#pragma unroll
        for (int t = 0; t < 4; t++) {
            int i = tid + (hb * 4 + t) * 256;
            int c = i >> 4, dq = (i & 15) << 2;
            size_t off = base + (size_t)c * (HH * DD) + dq;
            kr[t] = *(const float4*)(k + off);
            vr[t] = *(const float4*)(v + off);
        }
#pragma unroll
        for (int t = 0; t < 4; t++) {
            int i = tid + (hb * 4 + t) * 256;
            int c = i >> 4, dq = (i & 15) << 2;
            u32 ob = off128(c, dq * 2);
            *(uint2*)(sm_ + KN + ob) =
                make_uint2(rnd2h(phi(kr[t].x), phi(kr[t].y)),
                           rnd2h(phi(kr[t].z), phi(kr[t].w)));
            *(uint2*)(sm_ + VN + ob) =
                make_uint2(rnd2h(vr[t].x, vr[t].y), rnd2h(vr[t].z, vr[t].w));
        }
    }
    __syncthreads();

    int grp = lane >> 2, tg = lane & 3;
    int m0 = (wid >> 1) * 16, n0 = (wid & 1) * 32;
    int rAt = (lane & 7) + ((lane >> 4) & 1) * 8;
    int cAb = m0 * 2 + ((lane >> 3) & 1) * 16;
    int rBt = (lane & 7) + ((lane >> 3) & 1) * 8;
    int cBb = (lane >> 4) * 16;

    float acc[4][4] = {};
#pragma unroll
    for (int ks = 0; ks < 8; ks++) {
        u32 a0, a1, a2, a3;
        ldm4t(a0, a1, a2, a3, sb + VN + off128(ks * 16 + rAt, cAb));
#pragma unroll
        for (int jb = 0; jb < 2; jb++) {
            u32 b0, b1, b2, b3;
            ldm4t(b0, b1, b2, b3,
                  sb + KN + off128(ks * 16 + rBt, (n0 + jb * 16) * 2 + cBb));
            mma16816(acc[2 * jb],     a0, a1, a2, a3, b0, b1);
            mma16816(acc[2 * jb + 1], a0, a1, a2, a3, b2, b3);
        }
    }

    u32* kvout = g_kvh + (size_t)bid * (MM * DD / 2);
#pragma unroll
    for (int j = 0; j < 4; j++) {
        int dc = n0 + (j >> 1) * 16 + (j & 1) * 8 + tg * 2;
        kvout[(size_t)(m0 + grp) * 32 + (dc >> 1)]     = rnd2h(acc[j][0], acc[j][1]);
        kvout[(size_t)(m0 + grp + 8) * 32 + (dc >> 1)] = rnd2h(acc[j][2], acc[j][3]);
    }

    {
        float* ksp = (float*)(sm_ + KSP);
        int d = tid & 63, qd = tid >> 6;
        float s = 0.f;
#pragma unroll 8
        for (int cc = 0; cc < 32; cc++)
            s += __half2float(*(const __half*)(sm_ + KN + off128(qd * 32 + cc, d * 2)));
        ksp[qd * 64 + d] = s;
    }
    __syncthreads();
    if (tid < 64) {
        const float* ksp = (const float*)(sm_ + KSP);
        g_ksum[(size_t)bid * DD + tid] =
            ksp[tid] + ksp[64 + tid] + ksp[128 + tid] + ksp[192 + tid];
    }
}

// ---------------------------------------------------------------------------
// Kernel B: exclusive prefix over chunks (fp16 storage, fp32 accumulation)
// ---------------------------------------------------------------------------
__global__ void __launch_bounds__(256) prefix_kernel()
{
    int nh = blockIdx.x >> 2, qtr = blockIdx.x & 3;
    int n = nh / HH, h = nh % HH;
    int p2 = qtr * 256 + threadIdx.x;
    float4 run = make_float4(0.f, 0.f, 0.f, 0.f);
    for (int g = 0; g < GG; g++) {
        uint2* p = (uint2*)(g_kvh + (((size_t)(n * GG + g) * HH) + h) * (MM * DD / 2)) + p2;
        uint2 t = *p;
        float2 f0 = h2f(t.x), f1 = h2f(t.y);
        *p = make_uint2(rnd2h(run.x, run.y), rnd2h(run.z, run.w));
        run.x += f0.x; run.y += f0.y; run.z += f1.x; run.w += f1.y;
    }
    if (qtr == 0 && threadIdx.x < DD / 4) {
        float4 rs = make_float4(0.f, 0.f, 0.f, 0.f);
        for (int g = 0; g < GG; g++) {
            float4* p = (float4*)(g_ksum + (((size_t)(n * GG + g) * HH) + h) * DD) + threadIdx.x;
            float4 t = *p;
            *p = rs;
            rs.x += t.x; rs.y += t.y; rs.z += t.z; rs.w += t.w;
        }
    }
}

// ---------------------------------------------------------------------------
// Kernel C: fp16 2-pass, fp32 intra-z (no ones-plane), cp.async KV' copy,
// 3 CTAs/SM (73KB smem, 85-reg cap).
// planes: QH 0, QL 16K, KH 32K (128x128B); VN 48K (128x128B);
//         WH 64K KV'+ksum (72x128B).  total 73728 B.
// ---------------------------------------------------------------------------
#define QHo 0
#define QLo 16384
#define KHo 32768
#define VNo 49152
#define WHo 65536
#define SMEM_C 74752

__global__ void __launch_bounds__(256, 3) output_kernel(
    const float* __restrict__ q, const float* __restrict__ k,
    const float* __restrict__ v, float* __restrict__ out)
{
    extern __shared__ char sm_[];
    u32 sb = smem_u32(sm_);

    int tid = threadIdx.x, lane = tid & 31, wid = tid >> 5;
    int bid = blockIdx.x;
    int h = bid % HH;
    int gc = (bid / HH) % GG;
    int n = bid / (HH * GG);
    size_t base = (((size_t)n * LL + (size_t)gc * CC) * HH + h) * DD;

    // ---- KV' rows 0..63 via cp.async (512 x 16B, no register staging) ----
    {
        const u32* kvp = g_kvh + (size_t)bid * (MM * DD / 2);
#pragma unroll
        for (int t = 0; t < 2; t++) {
            int i = tid + t * 256;                    // 0..511
            int m = i >> 3, du = (i & 7) * 4;         // 16B-aligned
            u32 dst = sb + WHo + off128(m, du * 4);
            const void* src = kvp + (size_t)m * 32 + du;
            asm volatile("cp.async.ca.shared.global [%0], [%1], 16;"
                         :: "r"(dst), "l"(src));
        }
        asm volatile("cp.async.commit_group;");
    }

    // ---- merged, batched q/k/v loader (6 LDG.128 in flight per batch) ----
#pragma unroll
    for (int bb = 0; bb < 4; bb++) {
        float4 qr[2], kr[2], vr[2];
#pragma unroll
        for (int t = 0; t < 2; t++) {
            int i = tid + (bb * 2 + t) * 256;
            int c = i >> 4, dq = (i & 15) << 2;
            size_t off = base + (size_t)c * (HH * DD) + dq;
            qr[t] = *(const float4*)(q + off);
            kr[t] = *(const float4*)(k + off);
            vr[t] = *(const float4*)(v + off);
        }
#pragma unroll
        for (int t = 0; t < 2; t++) {
            int i = tid + (bb * 2 + t) * 256;
            int c = i >> 4, dq = (i & 15) << 2;
            u32 ob = off128(c, dq * 2);
            u32 h01, l01, h23, l23;
            split2h(phi(qr[t].x), phi(qr[t].y), h01, l01);
            split2h(phi(qr[t].z), phi(qr[t].w), h23, l23);
            *(uint2*)(sm_ + QHo + ob) = make_uint2(h01, h23);
            *(uint2*)(sm_ + QLo + ob) = make_uint2(l01, l23);
            *(uint2*)(sm_ + KHo + ob) =
                make_uint2(rnd2h(phi(kr[t].x), phi(kr[t].y)),
                           rnd2h(phi(kr[t].z), phi(kr[t].w)));
            *(uint2*)(sm_ + VNo + ob) =
                make_uint2(rnd2h(vr[t].x, vr[t].y), rnd2h(vr[t].z, vr[t].w));
        }
    }
    // ---- KV' row 64 = ksum_prev, rows 65..71 zero ----
    if (tid < 16) {
        float4 t4 = *(const float4*)(g_ksum + (size_t)bid * DD + tid * 4);
        *(uint2*)(sm_ + WHo + off128(64, tid * 8)) =
            make_uint2(rnd2h(t4.x, t4.y), rnd2h(t4.z, t4.w));
    }
    if (tid < 224) {
        int row = 65 + (tid >> 5), cu = tid & 31;
        *(u32*)(sm_ + WHo + row * 128 + cu * 4) = 0u;
    }
    asm volatile("cp.async.wait_group 0;" ::: "memory");
    __syncthreads();

    const int perm[8] = { 0, 1, 2, 3, 7, 6, 5, 4 };
    int wb = perm[wid];
    int m0 = wb * 16;
    int grp = lane >> 2, tg = lane & 3;
    int rA = m0 + ((lane >> 3) & 1) * 8 + (lane & 7);
    int rB = (lane >> 4) * 8 + (lane & 7);
    int kbA0 = 16 * (lane >> 4);
    int kbB0 = 16 * ((lane >> 3) & 1);
    int rBt = (lane & 7) + ((lane >> 3) & 1) * 8;   // natural-V trans B
    int cBb = (lane >> 4) * 16;
    int r9 = 64 + (lane & 7);                        // WH plane z row
    int r0 = m0 + grp, r1 = r0 + 8;

    // ---- cache Q fragments ----
    u32 qh[4][4], ql[4][4];
#pragma unroll
    for (int ks = 0; ks < 4; ks++) {
        ldm4(qh[ks][0], qh[ks][1], qh[ks][2], qh[ks][3], sb + QHo + off128(rA, 32 * ks + kbA0));
        ldm4(ql[ks][0], ql[ks][1], ql[ks][2], ql[ks][3], sb + QLo + off128(rA, 32 * ks + kbA0));
    }

    float accO[9][4] = {};

    // ---- inter: O += Q KV'^T (N=72, z col 64) ----
#pragma unroll
    for (int ks = 0; ks < 4; ks++) {
        int kb = 32 * ks + kbB0;
#pragma unroll
        for (int jb = 0; jb < 4; jb++) {
            u32 b0, b1, b2, b3;
            ldm4(b0, b1, b2, b3, sb + WHo + off128(jb * 16 + rB, kb));
            mma16816(accO[2 * jb],     qh[ks][0], qh[ks][1], qh[ks][2], qh[ks][3], b0, b1);
            mma16816(accO[2 * jb + 1], qh[ks][0], qh[ks][1], qh[ks][2], qh[ks][3], b2, b3);
            mma16816(accO[2 * jb],     ql[ks][0], ql[ks][1], ql[ks][2], ql[ks][3], b0, b1);
            mma16816(accO[2 * jb + 1], ql[ks][0], ql[ks][1], ql[ks][2], ql[ks][3], b2, b3);
        }
        u32 b0, b1;
        ldm2(b0, b1, sb + WHo + off128(r9, kb));
        mma16816(accO[8], qh[ks][0], qh[ks][1], qh[ks][2], qh[ks][3], b0, b1);
        mma16816(accO[8], ql[ks][0], ql[ks][1], ql[ks][2], ql[ks][3], b0, b1);
    }

    // ---- S blocks (jb <= wb): GEMM1 -> mask (+fp32 z) -> split -> intra ----
    float zs0 = 0.f, zs1 = 0.f;
#pragma unroll
    for (int jb = 0; jb < 8; jb++) {
        if (jb <= wb) {
            float s0[4] = {}, s1[4] = {};
#pragma unroll
            for (int ks = 0; ks < 4; ks++) {
                u32 b0, b1, b2, b3;
                ldm4(b0, b1, b2, b3, sb + KHo + off128(jb * 16 + rB, 32 * ks + kbB0));
                mma16816(s0, qh[ks][0], qh[ks][1], qh[ks][2], qh[ks][3], b0, b1);
                mma16816(s1, qh[ks][0], qh[ks][1], qh[ks][2], qh[ks][3], b2, b3);
                mma16816(s0, ql[ks][0], ql[ks][1], ql[ks][2], ql[ks][3], b0, b1);
                mma16816(s1, ql[ks][0], ql[ks][1], ql[ks][2], ql[ks][3], b2, b3);
            }
            int cA = jb * 16 + tg * 2, cB = cA + 8;
            if (cA > r0)     s0[0] = 0.f;
            if (cA + 1 > r0) s0[1] = 0.f;
            if (cA > r1)     s0[2] = 0.f;
            if (cA + 1 > r1) s0[3] = 0.f;
            if (cB > r0)     s1[0] = 0.f;
            if (cB + 1 > r0) s1[1] = 0.f;
            if (cB > r1)     s1[2] = 0.f;
            if (cB + 1 > r1) s1[3] = 0.f;
            zs0 += (s0[0] + s0[1]) + (s1[0] + s1[1]);
            zs1 += (s0[2] + s0[3]) + (s1[2] + s1[3]);
            u32 sh0, sh1, sh2, sh3, sl0, sl1, sl2, sl3;
            split2h(s0[0], s0[1], sh0, sl0);
            split2h(s0[2], s0[3], sh1, sl1);
            split2h(s1[0], s1[1], sh2, sl2);
            split2h(s1[2], s1[3], sh3, sl3);
#pragma unroll
            for (int vjb = 0; vjb < 4; vjb++) {
                u32 b0, b1, b2, b3;
                ldm4t(b0, b1, b2, b3,
                      sb + VNo + off128(jb * 16 + rBt, vjb * 32 + cBb));
                mma16816(accO[2 * vjb],     sh0, sh1, sh2, sh3, b0, b1);
                mma16816(accO[2 * vjb + 1], sh0, sh1, sh2, sh3, b2, b3);
                mma16816(accO[2 * vjb],     sl0, sl1, sl2, sl3, b0, b1);
                mma16816(accO[2 * vjb + 1], sl0, sl1, sl2, sl3, b2, b3);
            }
        }
    }
    // reduce intra z over the 4 tg lanes of each quad
    zs0 += __shfl_xor_sync(0xffffffffu, zs0, 1);
    zs0 += __shfl_xor_sync(0xffffffffu, zs0, 2);
    zs1 += __shfl_xor_sync(0xffffffffu, zs1, 1);
    zs1 += __shfl_xor_sync(0xffffffffu, zs1, 2);

    // ---- normalize + store (z = intra fp32 + inter col 64) ----
    float zr0 = __shfl_sync(0xffffffffu, accO[8][0], lane & 28);
    float zr1 = __shfl_sync(0xffffffffu, accO[8][2], lane & 28);
    float rz0 = 1.0f / (zr0 + zs0 + EPSF);
    float rz1 = 1.0f / (zr1 + zs1 + EPSF);
    float* op0 = out + (((size_t)n * LL + (size_t)gc * CC + r0) * HH + h) * MM;
    float* op1 = op0 + (size_t)8 * HH * MM;
#pragma unroll
    for (int j = 0; j < 8; j++) {
        int c0 = j * 8 + tg * 2;
        *(float2*)(op0 + c0) = make_float2(accO[j][0] * rz0, accO[j][1] * rz0);
        *(float2*)(op1 + c0) = make_float2(accO[j][2] * rz1, accO[j][3] * rz1);
    }
}

// ---------------------------------------------------------------------------
extern "C" void kernel_launch(void* const* d_in, const int* in_sizes, int n_in,
                              void* d_out, int out_size)
{
    const float* q = (const float*)d_in[0];
    const float* k = (const float*)d_in[1];
    const float* v = (const float*)d_in[2];
    float* out = (float*)d_out;

    const int SMEM_A = 33792;

    cudaFuncSetAttribute(chunk_state_kernel,
                         cudaFuncAttributeMaxDynamicSharedMemorySize, SMEM_A);
    cudaFuncSetAttribute(output_kernel,
                         cudaFuncAttributeMaxDynamicSharedMemorySize, SMEM_C);

    chunk_state_kernel<<<NN * GG * HH, 256, SMEM_A>>>(k, v);
    prefix_kernel<<<NN * HH * 4, 256>>>();
    output_kernel<<<NN * GG * HH, 256, SMEM_C>>>(q, k, v, out);
}

// round 14
// speedup vs baseline: 1.4113x; 1.1861x over previous
#include <cuda_runtime.h>
#include <cuda_fp16.h>
#include <math.h>
#include <stdint.h>

#define NN 4
#define LL 4096
#define HH 16
#define DD 64
#define MM 64
#define CC 128
#define GG 32
#define EPSF 1e-6f

typedef unsigned int u32;

// Scratch: per-chunk kvT stored as packed fp16 pairs (half2 along d) + fp32 ksum.
static __device__ u32   g_kvh[(size_t)NN * GG * HH * MM * (DD / 2)];   // 16.7MB
static __device__ float g_ksum[(size_t)NN * GG * HH * DD];

__device__ __forceinline__ float phi(float x) { return x > 0.f ? x + 1.f : __expf(x); }

__device__ __forceinline__ void split2h(float x0, float x1, u32& h, u32& l) {
    __half2 hh = __floats2half2_rn(x0, x1);
    float2 f = __half22float2(hh);
    __half2 ll = __floats2half2_rn(x0 - f.x, x1 - f.y);
    h = *reinterpret_cast<u32*>(&hh);
    l = *reinterpret_cast<u32*>(&ll);
}
__device__ __forceinline__ u32 rnd2h(float x0, float x1) {
    __half2 hh = __floats2half2_rn(x0, x1);
    return *reinterpret_cast<u32*>(&hh);
}
__device__ __forceinline__ float2 h2f(u32 u) {
    return __half22float2(*reinterpret_cast<__half2*>(&u));
}

__device__ __forceinline__ u32 smem_u32(const void* p) {
    u32 a;
    asm("{ .reg .u64 t; cvta.to.shared.u64 t, %1; cvt.u32.u64 %0, t; }" : "=r"(a) : "l"(p));
    return a;
}
__device__ __forceinline__ void ldm4(u32& r0, u32& r1, u32& r2, u32& r3, u32 a) {
    asm volatile("ldmatrix.sync.aligned.m8n8.x4.shared.b16 {%0,%1,%2,%3},[%4];"
                 : "=r"(r0), "=r"(r1), "=r"(r2), "=r"(r3) : "r"(a));
}
__device__ __forceinline__ void ldm4t(u32& r0, u32& r1, u32& r2, u32& r3, u32 a) {
    asm volatile("ldmatrix.sync.aligned.m8n8.x4.trans.shared.b16 {%0,%1,%2,%3},[%4];"
                 : "=r"(r0), "=r"(r1), "=r"(r2), "=r"(r3) : "r"(a));
}
__device__ __forceinline__ void ldm2(u32& r0, u32& r1, u32 a) {
    asm volatile("ldmatrix.sync.aligned.m8n8.x2.shared.b16 {%0,%1},[%2];"
                 : "=r"(r0), "=r"(r1) : "r"(a));
}
__device__ __forceinline__ void mma16816(float* d, u32 a0, u32 a1, u32 a2, u32 a3,
                                         u32 b0, u32 b1) {
    asm("mma.sync.aligned.m16n8k16.row.col.f32.f16.f16.f32 "
        "{%0,%1,%2,%3},{%4,%5,%6,%7},{%8,%9},{%0,%1,%2,%3};"
        : "+f"(d[0]), "+f"(d[1]), "+f"(d[2]), "+f"(d[3])
        : "r"(a0), "r"(a1), "r"(a2), "r"(a3), "r"(b0), "r"(b1));
}
__device__ __forceinline__ u32 off128(int row, int kb) {
    return (u32)(row * 128) + (u32)(((((kb >> 4) & 7) ^ (row & 7)) << 4) | (kb & 15));
}

// ---------------------------------------------------------------------------
// Kernel A: kvT[m][d] = sum_c v[c][m] * phi(k)[c][d]
// Natural [c][.] layout + ldmatrix.trans fragments. Batched LDG (MLP ~8).
// ---------------------------------------------------------------------------
__global__ void __launch_bounds__(256, 3) chunk_state_kernel(
    const float* __restrict__ k, const float* __restrict__ v)
{
    extern __shared__ char sm_[];
    const int KN = 0, VN = 16384, KSP = 32768;
    u32 sb = smem_u32(sm_);

    int tid = threadIdx.x, lane = tid & 31, wid = tid >> 5;
    int bid = blockIdx.x;
    int h = bid % HH;
    int gc = (bid / HH) % GG;
    int n = bid / (HH * GG);
    size_t base = (((size_t)n * LL + (size_t)gc * CC) * HH + h) * DD;

#pragma unroll
    for (int hb = 0; hb < 2; hb++) {
        float4 kr[4], vr[4];
#pragma unroll
        for (int t = 0; t < 4; t++) {
            int i = tid + (hb * 4 + t) * 256;
            int c = i >> 4, dq = (i & 15) << 2;
            size_t off = base + (size_t)c * (HH * DD) + dq;
            kr[t] = *(const float4*)(k + off);
            vr[t] = *(const float4*)(v + off);
        }
#pragma unroll
        for (int t = 0; t < 4; t++) {
            int i = tid + (hb * 4 + t) * 256;
            int c = i >> 4, dq = (i & 15) << 2;
            u32 ob = off128(c, dq * 2);
            *(uint2*)(sm_ + KN + ob) =
                make_uint2(rnd2h(phi(kr[t].x), phi(kr[t].y)),
                           rnd2h(phi(kr[t].z), phi(kr[t].w)));
            *(uint2*)(sm_ + VN + ob) =
                make_uint2(rnd2h(vr[t].x, vr[t].y), rnd2h(vr[t].z, vr[t].w));
        }
    }
    __syncthreads();

    int grp = lane >> 2, tg = lane & 3;
    int m0 = (wid >> 1) * 16, n0 = (wid & 1) * 32;
    int rAt = (lane & 7) + ((lane >> 4) & 1) * 8;
    int cAb = m0 * 2 + ((lane >> 3) & 1) * 16;
    int rBt = (lane & 7) + ((lane >> 3) & 1) * 8;
    int cBb = (lane >> 4) * 16;

    float acc[4][4] = {};
#pragma unroll
    for (int ks = 0; ks < 8; ks++) {
        u32 a0, a1, a2, a3;
        ldm4t(a0, a1, a2, a3, sb + VN + off128(ks * 16 + rAt, cAb));
#pragma unroll
        for (int jb = 0; jb < 2; jb++) {
            u32 b0, b1, b2, b3;
            ldm4t(b0, b1, b2, b3,
                  sb + KN + off128(ks * 16 + rBt, (n0 + jb * 16) * 2 + cBb));
            mma16816(acc[2 * jb],     a0, a1, a2, a3, b0, b1);
            mma16816(acc[2 * jb + 1], a0, a1, a2, a3, b2, b3);
        }
    }

    u32* kvout = g_kvh + (size_t)bid * (MM * DD / 2);
#pragma unroll
    for (int j = 0; j < 4; j++) {
        int dc = n0 + (j >> 1) * 16 + (j & 1) * 8 + tg * 2;
        kvout[(size_t)(m0 + grp) * 32 + (dc >> 1)]     = rnd2h(acc[j][0], acc[j][1]);
        kvout[(size_t)(m0 + grp + 8) * 32 + (dc >> 1)] = rnd2h(acc[j][2], acc[j][3]);
    }

    {
        float* ksp = (float*)(sm_ + KSP);
        int d = tid & 63, qd = tid >> 6;
        float s = 0.f;
#pragma unroll 8
        for (int cc = 0; cc < 32; cc++)
            s += __half2float(*(const __half*)(sm_ + KN + off128(qd * 32 + cc, d * 2)));
        ksp[qd * 64 + d] = s;
    }
    __syncthreads();
    if (tid < 64) {
        const float* ksp = (const float*)(sm_ + KSP);
        g_ksum[(size_t)bid * DD + tid] =
            ksp[tid] + ksp[64 + tid] + ksp[128 + tid] + ksp[192 + tid];
    }
}

// ---------------------------------------------------------------------------
// Kernel B: exclusive prefix over chunks (fp16 storage, fp32 accumulation)
// ---------------------------------------------------------------------------
__global__ void __launch_bounds__(256) prefix_kernel()
{
    int nh = blockIdx.x >> 2, qtr = blockIdx.x & 3;
    int n = nh / HH, h = nh % HH;
    int p2 = qtr * 256 + threadIdx.x;
    float4 run = make_float4(0.f, 0.f, 0.f, 0.f);
    for (int g = 0; g < GG; g++) {
        uint2* p = (uint2*)(g_kvh + (((size_t)(n * GG + g) * HH) + h) * (MM * DD / 2)) + p2;
        uint2 t = *p;
        float2 f0 = h2f(t.x), f1 = h2f(t.y);
        *p = make_uint2(rnd2h(run.x, run.y), rnd2h(run.z, run.w));
        run.x += f0.x; run.y += f0.y; run.z += f1.x; run.w += f1.y;
    }
    if (qtr == 0 && threadIdx.x < DD / 4) {
        float4 rs = make_float4(0.f, 0.f, 0.f, 0.f);
        for (int g = 0; g < GG; g++) {
            float4* p = (float4*)(g_ksum + (((size_t)(n * GG + g) * HH) + h) * DD) + threadIdx.x;
            float4 t = *p;
            *p = rs;
            rs.x += t.x; rs.y += t.y; rs.z += t.z; rs.w += t.w;
        }
    }
}

// ---------------------------------------------------------------------------
// Kernel C: fp16 1-pass Q/K/V/KV (rounded), 2-pass S (split) intra;
// fp32 intra-z, cp.async KV' copy, 3 CTAs/SM.
// planes: QH 0, KH 16K, VN 32K (128x128B); WH 48K KV'+ksum (72x128B).
// total 57 KB.
// ---------------------------------------------------------------------------
#define QHo 0
#define KHo 16384
#define VNo 32768
#define WHo 49152
#define SMEM_C 58368

__global__ void __launch_bounds__(256, 3) output_kernel(
    const float* __restrict__ q, const float* __restrict__ k,
    const float* __restrict__ v, float* __restrict__ out)
{
    extern __shared__ char sm_[];
    u32 sb = smem_u32(sm_);

    int tid = threadIdx.x, lane = tid & 31, wid = tid >> 5;
    int bid = blockIdx.x;
    int h = bid % HH;
    int gc = (bid / HH) % GG;
    int n = bid / (HH * GG);
    size_t base = (((size_t)n * LL + (size_t)gc * CC) * HH + h) * DD;

    // ---- KV' rows 0..63 via cp.async (512 x 16B) ----
    {
        const u32* kvp = g_kvh + (size_t)bid * (MM * DD / 2);
#pragma unroll
        for (int t = 0; t < 2; t++) {
            int i = tid + t * 256;
            int m = i >> 3, du = (i & 7) * 4;
            u32 dst = sb + WHo + off128(m, du * 4);
            const void* src = kvp + (size_t)m * 32 + du;
            asm volatile("cp.async.ca.shared.global [%0], [%1], 16;"
                         :: "r"(dst), "l"(src));
        }
        asm volatile("cp.async.commit_group;");
    }

    // ---- merged, batched q/k/v loader (all rounded to fp16) ----
#pragma unroll
    for (int bb = 0; bb < 4; bb++) {
        float4 qr[2], kr[2], vr[2];
#pragma unroll
        for (int t = 0; t < 2; t++) {
            int i = tid + (bb * 2 + t) * 256;
            int c = i >> 4, dq = (i & 15) << 2;
            size_t off = base + (size_t)c * (HH * DD) + dq;
            qr[t] = *(const float4*)(q + off);
            kr[t] = *(const float4*)(k + off);
            vr[t] = *(const float4*)(v + off);
        }
#pragma unroll
        for (int t = 0; t < 2; t++) {
            int i = tid + (bb * 2 + t) * 256;
            int c = i >> 4, dq = (i & 15) << 2;
            u32 ob = off128(c, dq * 2);
            *(uint2*)(sm_ + QHo + ob) =
                make_uint2(rnd2h(phi(qr[t].x), phi(qr[t].y)),
                           rnd2h(phi(qr[t].z), phi(qr[t].w)));
            *(uint2*)(sm_ + KHo + ob) =
                make_uint2(rnd2h(phi(kr[t].x), phi(kr[t].y)),
                           rnd2h(phi(kr[t].z), phi(kr[t].w)));
            *(uint2*)(sm_ + VNo + ob) =
                make_uint2(rnd2h(vr[t].x, vr[t].y), rnd2h(vr[t].z, vr[t].w));
        }
    }
    // ---- KV' row 64 = ksum_prev, rows 65..71 zero ----
    if (tid < 16) {
        float4 t4 = *(const float4*)(g_ksum + (size_t)bid * DD + tid * 4);
        *(uint2*)(sm_ + WHo + off128(64, tid * 8)) =
            make_uint2(rnd2h(t4.x, t4.y), rnd2h(t4.z, t4.w));
    }
    if (tid < 224) {
        int row = 65 + (tid >> 5), cu = tid & 31;
        *(u32*)(sm_ + WHo + row * 128 + cu * 4) = 0u;
    }
    asm volatile("cp.async.wait_group 0;" ::: "memory");
    __syncthreads();

    const int perm[8] = { 0, 1, 2, 3, 7, 6, 5, 4 };
    int wb = perm[wid];
    int m0 = wb * 16;
    int grp = lane >> 2, tg = lane & 3;
    int rA = m0 + ((lane >> 3) & 1) * 8 + (lane & 7);
    int rB = (lane >> 4) * 8 + (lane & 7);
    int kbA0 = 16 * (lane >> 4);
    int kbB0 = 16 * ((lane >> 3) & 1);
    int rBt = (lane & 7) + ((lane >> 3) & 1) * 8;   // natural-V trans B
    int cBb = (lane >> 4) * 16;
    int r9 = 64 + (lane & 7);
    int r0 = m0 + grp, r1 = r0 + 8;

    // ---- cache Q fragments (rounded, single pass) ----
    u32 qh[4][4];
#pragma unroll
    for (int ks = 0; ks < 4; ks++)
        ldm4(qh[ks][0], qh[ks][1], qh[ks][2], qh[ks][3], sb + QHo + off128(rA, 32 * ks + kbA0));

    float accO[9][4] = {};

    // ---- inter: O += Q KV'^T (N=72, z col 64) ----
#pragma unroll
    for (int ks = 0; ks < 4; ks++) {
        int kb = 32 * ks + kbB0;
#pragma unroll
        for (int jb = 0; jb < 4; jb++) {
            u32 b0, b1, b2, b3;
            ldm4(b0, b1, b2, b3, sb + WHo + off128(jb * 16 + rB, kb));
            mma16816(accO[2 * jb],     qh[ks][0], qh[ks][1], qh[ks][2], qh[ks][3], b0, b1);
            mma16816(accO[2 * jb + 1], qh[ks][0], qh[ks][1], qh[ks][2], qh[ks][3], b2, b3);
        }
        u32 b0, b1;
        ldm2(b0, b1, sb + WHo + off128(r9, kb));
        mma16816(accO[8], qh[ks][0], qh[ks][1], qh[ks][2], qh[ks][3], b0, b1);
    }

    // ---- S blocks (jb <= wb): GEMM1 -> mask (+fp32 z) -> split -> intra ----
    float zs0 = 0.f, zs1 = 0.f;
#pragma unroll
    for (int jb = 0; jb < 8; jb++) {
        if (jb <= wb) {
            float s0[4] = {}, s1[4] = {};
#pragma unroll
            for (int ks = 0; ks < 4; ks++) {
                u32 b0, b1, b2, b3;
                ldm4(b0, b1, b2, b3, sb + KHo + off128(jb * 16 + rB, 32 * ks + kbB0));
                mma16816(s0, qh[ks][0], qh[ks][1], qh[ks][2], qh[ks][3], b0, b1);
                mma16816(s1, qh[ks][0], qh[ks][1], qh[ks][2], qh[ks][3], b2, b3);
            }
            int cA = jb * 16 + tg * 2, cB = cA + 8;
            if (cA > r0)     s0[0] = 0.f;
            if (cA + 1 > r0) s0[1] = 0.f;
            if (cA > r1)     s0[2] = 0.f;
            if (cA + 1 > r1) s0[3] = 0.f;
            if (cB > r0)     s1[0] = 0.f;
            if (cB + 1 > r0) s1[1] = 0.f;
            if (cB > r1)     s1[2] = 0.f;
            if (cB + 1 > r1) s1[3] = 0.f;
            zs0 += (s0[0] + s0[1]) + (s1[0] + s1[1]);
            zs1 += (s0[2] + s0[3]) + (s1[2] + s1[3]);
            u32 sh0, sh1, sh2, sh3, sl0, sl1, sl2, sl3;
            split2h(s0[0], s0[1], sh0, sl0);
            split2h(s0[2], s0[3], sh1, sl1);
            split2h(s1[0], s1[1], sh2, sl2);
            split2h(s1[2], s1[3], sh3, sl3);
#pragma unroll
            for (int vjb = 0; vjb < 4; vjb++) {
                u32 b0, b1, b2, b3;
                ldm4t(b0, b1, b2, b3,
                      sb + VNo + off128(jb * 16 + rBt, vjb * 32 + cBb));
                mma16816(accO[2 * vjb],     sh0, sh1, sh2, sh3, b0, b1);
                mma16816(accO[2 * vjb + 1], sh0, sh1, sh2, sh3, b2, b3);
                mma16816(accO[2 * vjb],     sl0, sl1, sl2, sl3, b0, b1);
                mma16816(accO[2 * vjb + 1], sl0, sl1, sl2, sl3, b2, b3);
            }
        }
    }
    zs0 += __shfl_xor_sync(0xffffffffu, zs0, 1);
    zs0 += __shfl_xor_sync(0xffffffffu, zs0, 2);
    zs1 += __shfl_xor_sync(0xffffffffu, zs1, 1);
    zs1 += __shfl_xor_sync(0xffffffffu, zs1, 2);

    // ---- normalize + store ----
    float zr0 = __shfl_sync(0xffffffffu, accO[8][0], lane & 28);
    float zr1 = __shfl_sync(0xffffffffu, accO[8][2], lane & 28);
    float rz0 = 1.0f / (zr0 + zs0 + EPSF);
    float rz1 = 1.0f / (zr1 + zs1 + EPSF);
    float* op0 = out + (((size_t)n * LL + (size_t)gc * CC + r0) * HH + h) * MM;
    float* op1 = op0 + (size_t)8 * HH * MM;
#pragma unroll
    for (int j = 0; j < 8; j++) {
        int c0 = j * 8 + tg * 2;
        *(float2*)(op0 + c0) = make_float2(accO[j][0] * rz0, accO[j][1] * rz0);
        *(float2*)(op1 + c0) = make_float2(accO[j][2] * rz1, accO[j][3] * rz1);
    }
}

// ---------------------------------------------------------------------------
extern "C" void kernel_launch(void* const* d_in, const int* in_sizes, int n_in,
                              void* d_out, int out_size)
{
    const float* q = (const float*)d_in[0];
    const float* k = (const float*)d_in[1];
    const float* v = (const float*)d_in[2];
    float* out = (float*)d_out;

    const int SMEM_A = 33792;

    cudaFuncSetAttribute(chunk_state_kernel,
                         cudaFuncAttributeMaxDynamicSharedMemorySize, SMEM_A);
    cudaFuncSetAttribute(output_kernel,
                         cudaFuncAttributeMaxDynamicSharedMemorySize, SMEM_C);

    chunk_state_kernel<<<NN * GG * HH, 256, SMEM_A>>>(k, v);
    prefix_kernel<<<NN * HH * 4, 256>>>();
    output_kernel<<<NN * GG * HH, 256, SMEM_C>>>(q, k, v, out);
}

// round 15
// speedup vs baseline: 1.4525x; 1.0292x over previous
#include <cuda_runtime.h>
#include <cuda_fp16.h>
#include <math.h>
#include <stdint.h>

#define NN 4
#define LL 4096
#define HH 16
#define DD 64
#define MM 64
#define CC 128
#define GG 32
#define EPSF 1e-6f

typedef unsigned int u32;

// Scratch: per-chunk kvT stored as packed fp16 pairs (half2 along d) + fp32 ksum.
static __device__ u32   g_kvh[(size_t)NN * GG * HH * MM * (DD / 2)];   // 16.7MB
static __device__ float g_ksum[(size_t)NN * GG * HH * DD];

__device__ __forceinline__ float phi(float x) { return x > 0.f ? x + 1.f : __expf(x); }

__device__ __forceinline__ u32 rnd2h(float x0, float x1) {
    __half2 hh = __floats2half2_rn(x0, x1);
    return *reinterpret_cast<u32*>(&hh);
}
__device__ __forceinline__ float2 h2f(u32 u) {
    return __half22float2(*reinterpret_cast<__half2*>(&u));
}

__device__ __forceinline__ u32 smem_u32(const void* p) {
    u32 a;
    asm("{ .reg .u64 t; cvta.to.shared.u64 t, %1; cvt.u32.u64 %0, t; }" : "=r"(a) : "l"(p));
    return a;
}
__device__ __forceinline__ void ldm4(u32& r0, u32& r1, u32& r2, u32& r3, u32 a) {
    asm volatile("ldmatrix.sync.aligned.m8n8.x4.shared.b16 {%0,%1,%2,%3},[%4];"
                 : "=r"(r0), "=r"(r1), "=r"(r2), "=r"(r3) : "r"(a));
}
__device__ __forceinline__ void ldm4t(u32& r0, u32& r1, u32& r2, u32& r3, u32 a) {
    asm volatile("ldmatrix.sync.aligned.m8n8.x4.trans.shared.b16 {%0,%1,%2,%3},[%4];"
                 : "=r"(r0), "=r"(r1), "=r"(r2), "=r"(r3) : "r"(a));
}
__device__ __forceinline__ void ldm2(u32& r0, u32& r1, u32 a) {
    asm volatile("ldmatrix.sync.aligned.m8n8.x2.shared.b16 {%0,%1},[%2];"
                 : "=r"(r0), "=r"(r1) : "r"(a));
}
__device__ __forceinline__ void mma16816(float* d, u32 a0, u32 a1, u32 a2, u32 a3,
                                         u32 b0, u32 b1) {
    asm("mma.sync.aligned.m16n8k16.row.col.f32.f16.f16.f32 "
        "{%0,%1,%2,%3},{%4,%5,%6,%7},{%8,%9},{%0,%1,%2,%3};"
        : "+f"(d[0]), "+f"(d[1]), "+f"(d[2]), "+f"(d[3])
        : "r"(a0), "r"(a1), "r"(a2), "r"(a3), "r"(b0), "r"(b1));
}
__device__ __forceinline__ u32 off128(int row, int kb) {
    return (u32)(row * 128) + (u32)(((((kb >> 4) & 7) ^ (row & 7)) << 4) | (kb & 15));
}

// ---------------------------------------------------------------------------
// Kernel A: kvT[m][d] = sum_c v[c][m] * phi(k)[c][d]
// Natural [c][.] layout + ldmatrix.trans fragments. Batched LDG (MLP ~8).
// ---------------------------------------------------------------------------
__global__ void __launch_bounds__(256, 3) chunk_state_kernel(
    const float* __restrict__ k, const float* __restrict__ v)
{
    extern __shared__ char sm_[];
    const int KN = 0, VN = 16384, KSP = 32768;
    u32 sb = smem_u32(sm_);

    int tid = threadIdx.x, lane = tid & 31, wid = tid >> 5;
    int bid = blockIdx.x;
    int h = bid % HH;
    int gc = (bid / HH) % GG;
    int n = bid / (HH * GG);
    size_t base = (((size_t)n * LL + (size_t)gc * CC) * HH + h) * DD;

#pragma unroll
    for (int hb = 0; hb < 2; hb++) {
        float4 kr[4], vr[4];
#pragma unroll
        for (int t = 0; t < 4; t++) {
            int i = tid + (hb * 4 + t) * 256;
            int c = i >> 4, dq = (i & 15) << 2;
            size_t off = base + (size_t)c * (HH * DD) + dq;
            kr[t] = *(const float4*)(k + off);
            vr[t] = *(const float4*)(v + off);
        }
#pragma unroll
        for (int t = 0; t < 4; t++) {
            int i = tid + (hb * 4 + t) * 256;
            int c = i >> 4, dq = (i & 15) << 2;
            u32 ob = off128(c, dq * 2);
            *(uint2*)(sm_ + KN + ob) =
                make_uint2(rnd2h(phi(kr[t].x), phi(kr[t].y)),
                           rnd2h(phi(kr[t].z), phi(kr[t].w)));
            *(uint2*)(sm_ + VN + ob) =
                make_uint2(rnd2h(vr[t].x, vr[t].y), rnd2h(vr[t].z, vr[t].w));
        }
    }
    __syncthreads();

    int grp = lane >> 2, tg = lane & 3;
    int m0 = (wid >> 1) * 16, n0 = (wid & 1) * 32;
    int rAt = (lane & 7) + ((lane >> 4) & 1) * 8;
    int cAb = m0 * 2 + ((lane >> 3) & 1) * 16;
    int rBt = (lane & 7) + ((lane >> 3) & 1) * 8;
    int cBb = (lane >> 4) * 16;

    float acc[4][4] = {};
#pragma unroll
    for (int ks = 0; ks < 8; ks++) {
        u32 a0, a1, a2, a3;
        ldm4t(a0, a1, a2, a3, sb + VN + off128(ks * 16 + rAt, cAb));
#pragma unroll
        for (int jb = 0; jb < 2; jb++) {
            u32 b0, b1, b2, b3;
            ldm4t(b0, b1, b2, b3,
                  sb + KN + off128(ks * 16 + rBt, (n0 + jb * 16) * 2 + cBb));
            mma16816(acc[2 * jb],     a0, a1, a2, a3, b0, b1);
            mma16816(acc[2 * jb + 1], a0, a1, a2, a3, b2, b3);
        }
    }

    u32* kvout = g_kvh + (size_t)bid * (MM * DD / 2);
#pragma unroll
    for (int j = 0; j < 4; j++) {
        int dc = n0 + (j >> 1) * 16 + (j & 1) * 8 + tg * 2;
        kvout[(size_t)(m0 + grp) * 32 + (dc >> 1)]     = rnd2h(acc[j][0], acc[j][1]);
        kvout[(size_t)(m0 + grp + 8) * 32 + (dc >> 1)] = rnd2h(acc[j][2], acc[j][3]);
    }

    {
        float* ksp = (float*)(sm_ + KSP);
        int d = tid & 63, qd = tid >> 6;
        float s = 0.f;
#pragma unroll 8
        for (int cc = 0; cc < 32; cc++)
            s += __half2float(*(const __half*)(sm_ + KN + off128(qd * 32 + cc, d * 2)));
        ksp[qd * 64 + d] = s;
    }
    __syncthreads();
    if (tid < 64) {
        const float* ksp = (const float*)(sm_ + KSP);
        g_ksum[(size_t)bid * DD + tid] =
            ksp[tid] + ksp[64 + tid] + ksp[128 + tid] + ksp[192 + tid];
    }
}

// ---------------------------------------------------------------------------
// Kernel B: exclusive prefix over chunks (fp16 storage, fp32 accumulation)
// ---------------------------------------------------------------------------
__global__ void __launch_bounds__(256) prefix_kernel()
{
    int nh = blockIdx.x >> 2, qtr = blockIdx.x & 3;
    int n = nh / HH, h = nh % HH;
    int p2 = qtr * 256 + threadIdx.x;
    float4 run = make_float4(0.f, 0.f, 0.f, 0.f);
    for (int g = 0; g < GG; g++) {
        uint2* p = (uint2*)(g_kvh + (((size_t)(n * GG + g) * HH) + h) * (MM * DD / 2)) + p2;
        uint2 t = *p;
        float2 f0 = h2f(t.x), f1 = h2f(t.y);
        *p = make_uint2(rnd2h(run.x, run.y), rnd2h(run.z, run.w));
        run.x += f0.x; run.y += f0.y; run.z += f1.x; run.w += f1.y;
    }
    if (qtr == 0 && threadIdx.x < DD / 4) {
        float4 rs = make_float4(0.f, 0.f, 0.f, 0.f);
        for (int g = 0; g < GG; g++) {
            float4* p = (float4*)(g_ksum + (((size_t)(n * GG + g) * HH) + h) * DD) + threadIdx.x;
            float4 t = *p;
            *p = rs;
            rs.x += t.x; rs.y += t.y; rs.z += t.z; rs.w += t.w;
        }
    }
}

// ---------------------------------------------------------------------------
// Kernel C: pure fp16 MMA (Q/K/V/KV/S all rounded), fp32 z, cp.async KV',
// triangle skip, 3 CTAs/SM. planes: QH 0, KH 16K, VN 32K; WH 48K. 57KB.
// ---------------------------------------------------------------------------
#define QHo 0
#define KHo 16384
#define VNo 32768
#define WHo 49152
#define SMEM_C 58368

__global__ void __launch_bounds__(256, 3) output_kernel(
    const float* __restrict__ q, const float* __restrict__ k,
    const float* __restrict__ v, float* __restrict__ out)
{
    extern __shared__ char sm_[];
    u32 sb = smem_u32(sm_);

    int tid = threadIdx.x, lane = tid & 31, wid = tid >> 5;
    int bid = blockIdx.x;
    int h = bid % HH;
    int gc = (bid / HH) % GG;
    int n = bid / (HH * GG);
    size_t base = (((size_t)n * LL + (size_t)gc * CC) * HH + h) * DD;

    // ---- KV' rows 0..63 via cp.async (512 x 16B) ----
    {
        const u32* kvp = g_kvh + (size_t)bid * (MM * DD / 2);
#pragma unroll
        for (int t = 0; t < 2; t++) {
            int i = tid + t * 256;
            int m = i >> 3, du = (i & 7) * 4;
            u32 dst = sb + WHo + off128(m, du * 4);
            const void* src = kvp + (size_t)m * 32 + du;
            asm volatile("cp.async.ca.shared.global [%0], [%1], 16;"
                         :: "r"(dst), "l"(src));
        }
        asm volatile("cp.async.commit_group;");
    }

    // ---- merged, batched q/k/v loader (all rounded to fp16) ----
#pragma unroll
    for (int bb = 0; bb < 4; bb++) {
        float4 qr[2], kr[2], vr[2];
#pragma unroll
        for (int t = 0; t < 2; t++) {
            int i = tid + (bb * 2 + t) * 256;
            int c = i >> 4, dq = (i & 15) << 2;
            size_t off = base + (size_t)c * (HH * DD) + dq;
            qr[t] = *(const float4*)(q + off);
            kr[t] = *(const float4*)(k + off);
            vr[t] = *(const float4*)(v + off);
        }
#pragma unroll
        for (int t = 0; t < 2; t++) {
            int i = tid + (bb * 2 + t) * 256;
            int c = i >> 4, dq = (i & 15) << 2;
            u32 ob = off128(c, dq * 2);
            *(uint2*)(sm_ + QHo + ob) =
                make_uint2(rnd2h(phi(qr[t].x), phi(qr[t].y)),
                           rnd2h(phi(qr[t].z), phi(qr[t].w)));
            *(uint2*)(sm_ + KHo + ob) =
                make_uint2(rnd2h(phi(kr[t].x), phi(kr[t].y)),
                           rnd2h(phi(kr[t].z), phi(kr[t].w)));
            *(uint2*)(sm_ + VNo + ob) =
                make_uint2(rnd2h(vr[t].x, vr[t].y), rnd2h(vr[t].z, vr[t].w));
        }
    }
    // ---- KV' row 64 = ksum_prev, rows 65..71 zero ----
    if (tid < 16) {
        float4 t4 = *(const float4*)(g_ksum + (size_t)bid * DD + tid * 4);
        *(uint2*)(sm_ + WHo + off128(64, tid * 8)) =
            make_uint2(rnd2h(t4.x, t4.y), rnd2h(t4.z, t4.w));
    }
    if (tid < 224) {
        int row = 65 + (tid >> 5), cu = tid & 31;
        *(u32*)(sm_ + WHo + row * 128 + cu * 4) = 0u;
    }
    asm volatile("cp.async.wait_group 0;" ::: "memory");
    __syncthreads();

    const int perm[8] = { 0, 1, 2, 3, 7, 6, 5, 4 };
    int wb = perm[wid];
    int m0 = wb * 16;
    int grp = lane >> 2, tg = lane & 3;
    int rA = m0 + ((lane >> 3) & 1) * 8 + (lane & 7);
    int rB = (lane >> 4) * 8 + (lane & 7);
    int kbA0 = 16 * (lane >> 4);
    int kbB0 = 16 * ((lane >> 3) & 1);
    int rBt = (lane & 7) + ((lane >> 3) & 1) * 8;   // natural-V trans B
    int cBb = (lane >> 4) * 16;
    int r9 = 64 + (lane & 7);
    int r0 = m0 + grp, r1 = r0 + 8;

    // ---- cache Q fragments ----
    u32 qh[4][4];
#pragma unroll
    for (int ks = 0; ks < 4; ks++)
        ldm4(qh[ks][0], qh[ks][1], qh[ks][2], qh[ks][3], sb + QHo + off128(rA, 32 * ks + kbA0));

    float accO[9][4] = {};

    // ---- inter: O += Q KV'^T (N=72, z col 64) ----
#pragma unroll
    for (int ks = 0; ks < 4; ks++) {
        int kb = 32 * ks + kbB0;
#pragma unroll
        for (int jb = 0; jb < 4; jb++) {
            u32 b0, b1, b2, b3;
            ldm4(b0, b1, b2, b3, sb + WHo + off128(jb * 16 + rB, kb));
            mma16816(accO[2 * jb],     qh[ks][0], qh[ks][1], qh[ks][2], qh[ks][3], b0, b1);
            mma16816(accO[2 * jb + 1], qh[ks][0], qh[ks][1], qh[ks][2], qh[ks][3], b2, b3);
        }
        u32 b0, b1;
        ldm2(b0, b1, sb + WHo + off128(r9, kb));
        mma16816(accO[8], qh[ks][0], qh[ks][1], qh[ks][2], qh[ks][3], b0, b1);
    }

    // ---- S blocks (jb <= wb): GEMM1 -> mask (+fp32 z) -> round -> intra ----
    float zs0 = 0.f, zs1 = 0.f;
#pragma unroll
    for (int jb = 0; jb < 8; jb++) {
        if (jb <= wb) {
            float s0[4] = {}, s1[4] = {};
#pragma unroll
            for (int ks = 0; ks < 4; ks++) {
                u32 b0, b1, b2, b3;
                ldm4(b0, b1, b2, b3, sb + KHo + off128(jb * 16 + rB, 32 * ks + kbB0));
                mma16816(s0, qh[ks][0], qh[ks][1], qh[ks][2], qh[ks][3], b0, b1);
                mma16816(s1, qh[ks][0], qh[ks][1], qh[ks][2], qh[ks][3], b2, b3);
            }
            int cA = jb * 16 + tg * 2, cB = cA + 8;
            if (cA > r0)     s0[0] = 0.f;
            if (cA + 1 > r0) s0[1] = 0.f;
            if (cA > r1)     s0[2] = 0.f;
            if (cA + 1 > r1) s0[3] = 0.f;
            if (cB > r0)     s1[0] = 0.f;
            if (cB + 1 > r0) s1[1] = 0.f;
            if (cB > r1)     s1[2] = 0.f;
            if (cB + 1 > r1) s1[3] = 0.f;
            zs0 += (s0[0] + s0[1]) + (s1[0] + s1[1]);
            zs1 += (s0[2] + s0[3]) + (s1[2] + s1[3]);
            u32 sh0 = rnd2h(s0[0], s0[1]);
            u32 sh1 = rnd2h(s0[2], s0[3]);
            u32 sh2 = rnd2h(s1[0], s1[1]);
            u32 sh3 = rnd2h(s1[2], s1[3]);
#pragma unroll
            for (int vjb = 0; vjb < 4; vjb++) {
                u32 b0, b1, b2, b3;
                ldm4t(b0, b1, b2, b3,
                      sb + VNo + off128(jb * 16 + rBt, vjb * 32 + cBb));
                mma16816(accO[2 * vjb],     sh0, sh1, sh2, sh3, b0, b1);
                mma16816(accO[2 * vjb + 1], sh0, sh1, sh2, sh3, b2, b3);
            }
        }
    }
    zs0 += __shfl_xor_sync(0xffffffffu, zs0, 1);
    zs0 += __shfl_xor_sync(0xffffffffu, zs0, 2);
    zs1 += __shfl_xor_sync(0xffffffffu, zs1, 1);
    zs1 += __shfl_xor_sync(0xffffffffu, zs1, 2);

    // ---- normalize + store ----
    float zr0 = __shfl_sync(0xffffffffu, accO[8][0], lane & 28);
    float zr1 = __shfl_sync(0xffffffffu, accO[8][2], lane & 28);
    float rz0 = 1.0f / (zr0 + zs0 + EPSF);
    float rz1 = 1.0f / (zr1 + zs1 + EPSF);
    float* op0 = out + (((size_t)n * LL + (size_t)gc * CC + r0) * HH + h) * MM;
    float* op1 = op0 + (size_t)8 * HH * MM;
#pragma unroll
    for (int j = 0; j < 8; j++) {
        int c0 = j * 8 + tg * 2;
        *(float2*)(op0 + c0) = make_float2(accO[j][0] * rz0, accO[j][1] * rz0);
        *(float2*)(op1 + c0) = make_float2(accO[j][2] * rz1, accO[j][3] * rz1);
    }
}

// ---------------------------------------------------------------------------
extern "C" void kernel_launch(void* const* d_in, const int* in_sizes, int n_in,
                              void* d_out, int out_size)
{
    const float* q = (const float*)d_in[0];
    const float* k = (const float*)d_in[1];
    const float* v = (const float*)d_in[2];
    float* out = (float*)d_out;

    const int SMEM_A = 33792;

    cudaFuncSetAttribute(chunk_state_kernel,
                         cudaFuncAttributeMaxDynamicSharedMemorySize, SMEM_A);
    cudaFuncSetAttribute(output_kernel,
                         cudaFuncAttributeMaxDynamicSharedMemorySize, SMEM_C);

    chunk_state_kernel<<<NN * GG * HH, 256, SMEM_A>>>(k, v);
    prefix_kernel<<<NN * HH * 4, 256>>>();
    output_kernel<<<NN * GG * HH, 256, SMEM_C>>>(q, k, v, out);
}